// round 7
// baseline (speedup 1.0000x reference)
#include <cuda_runtime.h>
#include <cstdint>

#define N_SEQ   2048
#define D_MODEL 1024
#define ATTN_SCALE 0.125f

// ---------------- scratch ----------------------------------------------------
__device__ float g_x [N_SEQ * D_MODEL];
__device__ float g_Wq[D_MODEL * D_MODEL];
__device__ float g_Wk[D_MODEL * D_MODEL];
__device__ float g_Wv[D_MODEL * D_MODEL];
__device__ float g_Wo[D_MODEL * D_MODEL];
__device__ float g_Q [N_SEQ * D_MODEL];
__device__ float g_K [N_SEQ * D_MODEL];
__device__ float g_V [N_SEQ * D_MODEL];
__device__ float g_Vt[D_MODEL * N_SEQ];
__device__ float g_AO[N_SEQ * D_MODEL];

// ---------------- helpers ----------------------------------------------------
__device__ __forceinline__ uint32_t f2tf(float x) {
    uint32_t y;
    asm("cvt.rna.tf32.f32 %0, %1;" : "=r"(y) : "f"(x));
    return y;
}
__device__ __forceinline__ float rtf(float x) { return __uint_as_float(f2tf(x)); }

__device__ __forceinline__ void mma_tf32(float c[4], const uint32_t a[4], const uint32_t b[2]) {
    asm volatile(
        "mma.sync.aligned.m16n8k8.row.col.f32.tf32.tf32.f32 "
        "{%0,%1,%2,%3}, {%4,%5,%6,%7}, {%8,%9}, {%0,%1,%2,%3};\n"
        : "+f"(c[0]), "+f"(c[1]), "+f"(c[2]), "+f"(c[3])
        : "r"(a[0]), "r"(a[1]), "r"(a[2]), "r"(a[3]), "r"(b[0]), "r"(b[1]));
}
__device__ __forceinline__ void ldsm4(uint32_t r[4], uint32_t addr) {
    asm volatile("ldmatrix.sync.aligned.m8n8.x4.shared.b16 {%0,%1,%2,%3}, [%4];"
                 : "=r"(r[0]), "=r"(r[1]), "=r"(r[2]), "=r"(r[3]) : "r"(addr));
}
#define CP16(dst, src) asm volatile("cp.async.cg.shared.global [%0], [%1], 16;" :: "r"(dst), "l"(src))
#define CPC            asm volatile("cp.async.commit_group;")
#define CPW(n)         asm volatile("cp.async.wait_group %0;" :: "n"(n))

// ---------------- prep: round inputs to tf32 once ---------------------------
__global__ __launch_bounds__(256) void prep_kernel(
    const float4* __restrict__ x,
    const float4* __restrict__ Wq, const float4* __restrict__ Wk,
    const float4* __restrict__ Wv, const float4* __restrict__ Wo) {
    const float4* src; float4* dst; int n4;
    switch (blockIdx.y) {
        case 0:  src = x;  dst = (float4*)g_x;  n4 = 524288; break;
        case 1:  src = Wq; dst = (float4*)g_Wq; n4 = 262144; break;
        case 2:  src = Wk; dst = (float4*)g_Wk; n4 = 262144; break;
        case 3:  src = Wv; dst = (float4*)g_Wv; n4 = 262144; break;
        default: src = Wo; dst = (float4*)g_Wo; n4 = 262144; break;
    }
    int i = blockIdx.x * 256 + threadIdx.x;
    if (i < n4) {
        float4 v = src[i];
        v.x = rtf(v.x); v.y = rtf(v.y); v.z = rtf(v.z); v.w = rtf(v.w);
        dst[i] = v;
    }
}

// ---------------- V transpose ------------------------------------------------
__global__ __launch_bounds__(256) void transposeV_kernel() {
    __shared__ float t[32][33];
    const int tx = threadIdx.x & 31, ty = threadIdx.x >> 5;
    const int bx = blockIdx.x, by = blockIdx.y;
#pragma unroll
    for (int j = 0; j < 4; j++)
        t[ty + j * 8][tx] = g_V[(size_t)(by * 32 + ty + j * 8) * D_MODEL + bx * 32 + tx];
    __syncthreads();
#pragma unroll
    for (int j = 0; j < 4; j++)
        g_Vt[(size_t)(bx * 32 + ty + j * 8) * N_SEQ + by * 32 + tx] = t[tx][ty + j * 8];
}

// ---------------- GEMM v2: 4 warps, 64x64 warp tile, K-step 16 ---------------
// C[M,1024] = A @ W^T + bias. 2 CTAs/SM (40KB smem, 128 threads).
#define GPAD2 20
#define GSTG  (128 * GPAD2)            // words per matrix per stage
#define GEMM_SMEM2 (4 * GSTG * 4)      // A0,A1,B0,B1 = 40960 B

template <bool ROUND>
__device__ __forceinline__ void gemm_body(const float* __restrict__ A, const float* __restrict__ W,
                                          const float* __restrict__ bias, float* __restrict__ C) {
    extern __shared__ uint32_t dsm[];
    const uint32_t sb = (uint32_t)__cvta_generic_to_shared(dsm);
    const int tid = threadIdx.x, warp = tid >> 5, lane = tid & 31;
    const int grp = lane >> 2, four = lane & 3;
    const int wm = warp >> 1, wn = warp & 1;
    const int m0 = blockIdx.x * 128, n0 = blockIdx.y * 128;

    float acc[4][8][4];
#pragma unroll
    for (int mi = 0; mi < 4; mi++)
#pragma unroll
        for (int ni = 0; ni < 8; ni++)
#pragma unroll
            for (int j = 0; j < 4; j++) acc[mi][ni][j] = 0.f;

    const int lr = tid >> 2, lc = (tid & 3) << 2;   // load row (+i*32), col word

#pragma unroll 1
    for (int kt = -1; kt < 64; kt++) {
        if (kt < 63) {
            const int s = (kt + 1) & 1, k0 = (kt + 1) * 16;
#pragma unroll
            for (int i = 0; i < 4; i++) {
                int r = lr + i * 32;
                CP16(sb + (s * GSTG + r * GPAD2 + lc) * 4,
                     A + (size_t)(m0 + r) * D_MODEL + k0 + lc);
                CP16(sb + ((2 + s) * GSTG + r * GPAD2 + lc) * 4,
                     W + (size_t)(n0 + r) * D_MODEL + k0 + lc);
            }
            CPC;
        }
        if (kt < 0) continue;
        if (kt < 63) { CPW(1); } else { CPW(0); }
        __syncthreads();

        const int s = kt & 1;
        const uint32_t abase = sb + (s * GSTG + (wm * 64 + (lane & 15)) * GPAD2 + ((lane >> 4) << 2)) * 4;
        const uint32_t bbase = sb + ((2 + s) * GSTG +
                        (wn * 64 + ((lane >> 4) << 3) + (lane & 7)) * GPAD2 + (((lane >> 3) & 1) << 2)) * 4;
#pragma unroll
        for (int kk = 0; kk < 16; kk += 8) {
            uint32_t a[4][4], bb[4][4];
#pragma unroll
            for (int mi = 0; mi < 4; mi++) ldsm4(a[mi], abase + (mi * 16 * GPAD2 + kk) * 4);
#pragma unroll
            for (int p = 0; p < 4; p++)   ldsm4(bb[p], bbase + (p * 16 * GPAD2 + kk) * 4);
#pragma unroll
            for (int mi = 0; mi < 4; mi++)
#pragma unroll
                for (int ni = 0; ni < 8; ni++)
                    mma_tf32(acc[mi][ni], a[mi], &bb[ni >> 1][(ni & 1) << 1]);
        }
        __syncthreads();
    }

#pragma unroll
    for (int mi = 0; mi < 4; mi++) {
        int r = m0 + wm * 64 + mi * 16 + grp;
#pragma unroll
        for (int ni = 0; ni < 8; ni++) {
            int c = n0 + wn * 64 + ni * 8 + (four << 1);
            float b0 = bias[c], b1 = bias[c + 1];
            float2 v0, v1;
            v0.x = acc[mi][ni][0] + b0; v0.y = acc[mi][ni][1] + b1;
            v1.x = acc[mi][ni][2] + b0; v1.y = acc[mi][ni][3] + b1;
            if (ROUND) { v0.x = rtf(v0.x); v0.y = rtf(v0.y); v1.x = rtf(v1.x); v1.y = rtf(v1.y); }
            *(float2*)(C + (size_t)r * D_MODEL + c)       = v0;
            *(float2*)(C + (size_t)(r + 8) * D_MODEL + c) = v1;
        }
    }
}

__global__ __launch_bounds__(128, 2) void qkv_gemm_kernel(
    const float* __restrict__ bq, const float* __restrict__ bk, const float* __restrict__ bv) {
    const float* W; const float* b; float* C;
    if (blockIdx.z == 0)      { W = g_Wq; b = bq; C = g_Q; }
    else if (blockIdx.z == 1) { W = g_Wk; b = bk; C = g_K; }
    else                      { W = g_Wv; b = bv; C = g_V; }
    gemm_body<true>(g_x, W, b, C);
}

__global__ __launch_bounds__(128, 2) void out_gemm_kernel(
    const float* __restrict__ bo, float* __restrict__ out) {
    gemm_body<false>(g_AO, g_Wo, bo, out);
}

// ---------------- attention (R6, proven: 4 warps x 32 q-rows) -----------------
#define APAD 68
#define QS_OFF 0
#define KS_OFF (128 * APAD)
#define VS_OFF (192 * APAD)
#define PS_OFF (256 * APAD)
#define ATTN_SMEM (384 * APAD * 4)

__global__ __launch_bounds__(128, 2) void attn_kernel(const float* __restrict__ dbias) {
    extern __shared__ uint32_t dsm[];
    const uint32_t sb = (uint32_t)__cvta_generic_to_shared(dsm);
    const int h = blockIdx.x, q0 = blockIdx.y * 128;
    const int tid = threadIdx.x, warp = tid >> 5, lane = tid & 31;
    const int grp = lane >> 2, four = lane & 3;
    const int mb = warp * 32;

    const int qlr = tid >> 4, qlc = (tid & 15) << 2;

#pragma unroll
    for (int i = 0; i < 16; i++) {
        int r = qlr + i * 8;
        CP16(sb + (QS_OFF + r * APAD + qlc) * 4, g_Q + (size_t)(q0 + r) * D_MODEL + h * 64 + qlc);
    }
    CPC;

    float Of[2][8][4], Or[2][8][4];
#pragma unroll
    for (int mi = 0; mi < 2; mi++)
#pragma unroll
        for (int ni = 0; ni < 8; ni++)
#pragma unroll
            for (int j = 0; j < 4; j++) { Of[mi][ni][j] = 0.f; Or[mi][ni][j] = 0.f; }
    float lsum[2][2] = {{0.f, 0.f}, {0.f, 0.f}};

    const float* brow[2][2];
#pragma unroll
    for (int mi = 0; mi < 2; mi++) {
        brow[mi][0] = dbias + (size_t)(q0 + mb + mi * 16 + grp) * N_SEQ;
        brow[mi][1] = brow[mi][0] + (size_t)8 * N_SEQ;
    }

    uint32_t qab[2], pab[2];
#pragma unroll
    for (int mi = 0; mi < 2; mi++) {
        qab[mi] = sb + (QS_OFF + (mb + mi * 16 + (lane & 15)) * APAD + ((lane >> 4) << 2)) * 4;
        pab[mi] = sb + (PS_OFF + (mb + mi * 16 + (lane & 15)) * APAD + ((lane >> 4) << 2)) * 4;
    }
    const uint32_t kbb = sb + (KS_OFF + (((lane >> 4) << 3) + (lane & 7)) * APAD + (((lane >> 3) & 1) << 2)) * 4;
    const uint32_t vbb = sb + (VS_OFF + (((lane >> 4) << 3) + (lane & 7)) * APAD + (((lane >> 3) & 1) << 2)) * 4;

#pragma unroll 1
    for (int kc = 0; kc < 32; kc++) {
        const int key0 = kc * 64;
        __syncthreads();
#pragma unroll
        for (int i = 0; i < 8; i++) {
            int r = qlr + i * 8;
            CP16(sb + (KS_OFF + r * APAD + qlc) * 4,
                 g_K + (size_t)(key0 + r) * D_MODEL + h * 64 + qlc);
        }
        CPC;
#pragma unroll
        for (int i = 0; i < 8; i++) {
            int r = qlr + i * 8;
            CP16(sb + (VS_OFF + r * APAD + qlc) * 4,
                 g_Vt + (size_t)(h * 64 + r) * N_SEQ + key0 + qlc);
        }
        CPC;
        CPW(1);
        __syncthreads();

        float s[2][8][4];
#pragma unroll
        for (int mi = 0; mi < 2; mi++)
#pragma unroll
            for (int ni = 0; ni < 8; ni++)
#pragma unroll
                for (int j = 0; j < 4; j++) s[mi][ni][j] = 0.f;
#pragma unroll
        for (int kk = 0; kk < 64; kk += 8) {
            uint32_t a[2][4], bb[4][4];
#pragma unroll
            for (int mi = 0; mi < 2; mi++) ldsm4(a[mi], qab[mi] + kk * 4);
#pragma unroll
            for (int p = 0; p < 4; p++) ldsm4(bb[p], kbb + (p * 16 * APAD + kk) * 4);
#pragma unroll
            for (int mi = 0; mi < 2; mi++)
#pragma unroll
                for (int ni = 0; ni < 8; ni++)
                    mma_tf32(s[mi][ni], a[mi], &bb[ni >> 1][(ni & 1) << 1]);
        }

#pragma unroll
        for (int mi = 0; mi < 2; mi++) {
#pragma unroll
            for (int ni = 0; ni < 8; ni++) {
                int c = ni * 8 + (four << 1);
                float2 bA = *(const float2*)(brow[mi][0] + key0 + c);
                float2 bB = *(const float2*)(brow[mi][1] + key0 + c);
                float p0 = __expf(fmaf(s[mi][ni][0], ATTN_SCALE, -bA.x));
                float p1 = __expf(fmaf(s[mi][ni][1], ATTN_SCALE, -bA.y));
                float p2 = __expf(fmaf(s[mi][ni][2], ATTN_SCALE, -bB.x));
                float p3 = __expf(fmaf(s[mi][ni][3], ATTN_SCALE, -bB.y));
                lsum[mi][0] += p0 + p1; lsum[mi][1] += p2 + p3;
                uint2 u0; u0.x = f2tf(p0); u0.y = f2tf(p1);
                uint2 u1; u1.x = f2tf(p2); u1.y = f2tf(p3);
                *(uint2*)(dsm + PS_OFF + (mb + mi * 16 + grp) * APAD + c)     = u0;
                *(uint2*)(dsm + PS_OFF + (mb + mi * 16 + grp + 8) * APAD + c) = u1;
            }
        }
        __syncwarp();

        CPW(0);
        __syncthreads();

#pragma unroll
        for (int kk = 0; kk < 64; kk += 8) {
            uint32_t a[2][4], bb[4][4];
#pragma unroll
            for (int mi = 0; mi < 2; mi++) ldsm4(a[mi], pab[mi] + kk * 4);
#pragma unroll
            for (int p = 0; p < 4; p++) ldsm4(bb[p], vbb + (p * 16 * APAD + kk) * 4);
#pragma unroll
            for (int mi = 0; mi < 2; mi++)
#pragma unroll
                for (int ni = 0; ni < 8; ni++)
                    mma_tf32(Or[mi][ni], a[mi], &bb[ni >> 1][(ni & 1) << 1]);
        }

        if ((kc & 3) == 3) {
#pragma unroll
            for (int mi = 0; mi < 2; mi++) {
                float L0 = lsum[mi][0], L1 = lsum[mi][1];
                L0 += __shfl_xor_sync(0xffffffffu, L0, 1);
                L0 += __shfl_xor_sync(0xffffffffu, L0, 2);
                L1 += __shfl_xor_sync(0xffffffffu, L1, 1);
                L1 += __shfl_xor_sync(0xffffffffu, L1, 2);
                float i0 = 1.0f / L0, i1 = 1.0f / L1;
#pragma unroll
                for (int ni = 0; ni < 8; ni++) {
                    Of[mi][ni][0] += Or[mi][ni][0] * i0;
                    Of[mi][ni][1] += Or[mi][ni][1] * i0;
                    Of[mi][ni][2] += Or[mi][ni][2] * i1;
                    Of[mi][ni][3] += Or[mi][ni][3] * i1;
                    Or[mi][ni][0] = Or[mi][ni][1] = Or[mi][ni][2] = Or[mi][ni][3] = 0.f;
                }
                lsum[mi][0] = 0.f; lsum[mi][1] = 0.f;
            }
        }
    }

    const float r8 = 1.0f / (8.0f + 1e-8f);
#pragma unroll
    for (int mi = 0; mi < 2; mi++) {
#pragma unroll
        for (int ni = 0; ni < 8; ni++) {
            int c = h * 64 + ni * 8 + (four << 1);
            float2 v0, v1;
            v0.x = rtf(Of[mi][ni][0] * r8); v0.y = rtf(Of[mi][ni][1] * r8);
            v1.x = rtf(Of[mi][ni][2] * r8); v1.y = rtf(Of[mi][ni][3] * r8);
            *(float2*)(g_AO + (size_t)(q0 + mb + mi * 16 + grp) * D_MODEL + c)     = v0;
            *(float2*)(g_AO + (size_t)(q0 + mb + mi * 16 + grp + 8) * D_MODEL + c) = v1;
        }
    }
}

// ---------------- launch -----------------------------------------------------
extern "C" void kernel_launch(void* const* d_in, const int* in_sizes, int n_in,
                              void* d_out, int out_size) {
    const float* x  = (const float*)d_in[0];
    const float* db = (const float*)d_in[1];
    const float* Wq = (const float*)d_in[2];
    const float* bq = (const float*)d_in[3];
    const float* Wk = (const float*)d_in[4];
    const float* bk = (const float*)d_in[5];
    const float* Wv = (const float*)d_in[6];
    const float* bv = (const float*)d_in[7];
    const float* Wo = (const float*)d_in[8];
    const float* bo = (const float*)d_in[9];
    float* out = (float*)d_out;

    cudaFuncSetAttribute(qkv_gemm_kernel, cudaFuncAttributeMaxDynamicSharedMemorySize, GEMM_SMEM2);
    cudaFuncSetAttribute(out_gemm_kernel, cudaFuncAttributeMaxDynamicSharedMemorySize, GEMM_SMEM2);
    cudaFuncSetAttribute(attn_kernel,     cudaFuncAttributeMaxDynamicSharedMemorySize, ATTN_SMEM);

    prep_kernel<<<dim3(2048, 5), 256>>>((const float4*)x, (const float4*)Wq,
                                        (const float4*)Wk, (const float4*)Wv,
                                        (const float4*)Wo);
    qkv_gemm_kernel<<<dim3(16, 8, 3), 128, GEMM_SMEM2>>>(bq, bk, bv);
    transposeV_kernel<<<dim3(32, 64), 256>>>();
    attn_kernel<<<dim3(16, 16), 128, ATTN_SMEM>>>(db);
    out_gemm_kernel<<<dim3(16, 8), 128, GEMM_SMEM2>>>(bo, out);
}

// round 8
// speedup vs baseline: 1.7009x; 1.7009x over previous
#include <cuda_runtime.h>
#include <cuda_fp16.h>
#include <cstdint>

#define N_SEQ   2048
#define D_MODEL 1024
#define ATTN_SCALE 0.125f

// ---------------- scratch (fp16 operands, fp32 accumulation everywhere) -------
__device__ __half g_xh [N_SEQ * D_MODEL];
__device__ __half g_Wqh[D_MODEL * D_MODEL];
__device__ __half g_Wkh[D_MODEL * D_MODEL];
__device__ __half g_Wvh[D_MODEL * D_MODEL];
__device__ __half g_Woh[D_MODEL * D_MODEL];
__device__ __half g_Qh [N_SEQ * D_MODEL];
__device__ __half g_Kh [N_SEQ * D_MODEL];
__device__ __half g_Vh [N_SEQ * D_MODEL];
__device__ __half g_Vth[D_MODEL * N_SEQ];     // transposed V, [d][token]
__device__ __half g_AOh[N_SEQ * D_MODEL];

// ---------------- helpers ------------------------------------------------------
__device__ __forceinline__ void mma_f16(float c[4], const uint32_t a[4], const uint32_t b[2]) {
    asm volatile(
        "mma.sync.aligned.m16n8k16.row.col.f32.f16.f16.f32 "
        "{%0,%1,%2,%3}, {%4,%5,%6,%7}, {%8,%9}, {%0,%1,%2,%3};\n"
        : "+f"(c[0]), "+f"(c[1]), "+f"(c[2]), "+f"(c[3])
        : "r"(a[0]), "r"(a[1]), "r"(a[2]), "r"(a[3]), "r"(b[0]), "r"(b[1]));
}
__device__ __forceinline__ void ldsm4(uint32_t r[4], uint32_t addr) {
    asm volatile("ldmatrix.sync.aligned.m8n8.x4.shared.b16 {%0,%1,%2,%3}, [%4];"
                 : "=r"(r[0]), "=r"(r[1]), "=r"(r[2]), "=r"(r[3]) : "r"(addr));
}
#define CP16(dst, src) asm volatile("cp.async.cg.shared.global [%0], [%1], 16;" :: "r"(dst), "l"(src))
#define CPC            asm volatile("cp.async.commit_group;")
#define CPW(n)         asm volatile("cp.async.wait_group %0;" :: "n"(n))

// swizzled byte address: 128B rows, 8 x 16B chunks, chunk ^= (row & 7)
__device__ __forceinline__ uint32_t swad(uint32_t base, int row, int chunk) {
    return base + row * 128 + (((chunk) ^ (row & 7)) << 4);
}
__device__ __forceinline__ uint32_t packh2(float a, float b) {
    __half2 h = __floats2half2_rn(a, b);
    return *(uint32_t*)&h;
}

// ---------------- prep: f32 -> fp16 --------------------------------------------
__global__ __launch_bounds__(256) void prep_kernel(
    const float4* __restrict__ x,
    const float4* __restrict__ Wq, const float4* __restrict__ Wk,
    const float4* __restrict__ Wv, const float4* __restrict__ Wo) {
    const float4* src; __half2* dst; int n4;
    switch (blockIdx.y) {
        case 0:  src = x;  dst = (__half2*)g_xh;  n4 = 524288; break;
        case 1:  src = Wq; dst = (__half2*)g_Wqh; n4 = 262144; break;
        case 2:  src = Wk; dst = (__half2*)g_Wkh; n4 = 262144; break;
        case 3:  src = Wv; dst = (__half2*)g_Wvh; n4 = 262144; break;
        default: src = Wo; dst = (__half2*)g_Woh; n4 = 262144; break;
    }
    int i = blockIdx.x * 256 + threadIdx.x;
    if (i < n4) {
        float4 v = src[i];
        dst[2 * i]     = __floats2half2_rn(v.x, v.y);
        dst[2 * i + 1] = __floats2half2_rn(v.z, v.w);
    }
}

// ---------------- V transpose (half) --------------------------------------------
__global__ __launch_bounds__(256) void transposeV_kernel() {
    __shared__ __half t[32][33];
    const int tx = threadIdx.x & 31, ty = threadIdx.x >> 5;
    const int bx = blockIdx.x, by = blockIdx.y;
#pragma unroll
    for (int j = 0; j < 4; j++)
        t[ty + j * 8][tx] = g_Vh[(size_t)(by * 32 + ty + j * 8) * D_MODEL + bx * 32 + tx];
    __syncthreads();
#pragma unroll
    for (int j = 0; j < 4; j++)
        g_Vth[(size_t)(bx * 32 + ty + j * 8) * N_SEQ + by * 32 + tx] = t[tx][ty + j * 8];
}

// ---------------- GEMM fp16: C[M,1024] = A @ W^T + bias -------------------------
// 8 warps (2x4), warp tile 64x32, K-step 64 fp16, double-buffered. smem 64KB.
#define G_A(s)  ((s) * 16384)
#define G_B(s)  (32768 + (s) * 16384)
#define GEMM_SMEM 65536

template <bool HALF_OUT>
__device__ __forceinline__ void gemm_body(const __half* __restrict__ A, const __half* __restrict__ W,
                                          const float* __restrict__ bias, void* __restrict__ Cv) {
    extern __shared__ __align__(128) char smc[];
    const uint32_t sb = (uint32_t)__cvta_generic_to_shared(smc);
    const int tid = threadIdx.x, warp = tid >> 5, lane = tid & 31;
    const int grp = lane >> 2, four = lane & 3;
    const int wm = warp >> 2, wn = warp & 3;
    const int m0 = blockIdx.x * 128, n0 = blockIdx.y * 128;

    float acc[4][4][4];
#pragma unroll
    for (int mi = 0; mi < 4; mi++)
#pragma unroll
        for (int ni = 0; ni < 4; ni++)
#pragma unroll
            for (int j = 0; j < 4; j++) acc[mi][ni][j] = 0.f;

    const int lr = tid >> 3, lj = tid & 7;      // loader: row (+i*32), chunk

    // fragment row bases (stage-invariant parts)
    const int arow = wm * 64 + (lane & 15);     // + mi*16
    const int acho = lane >> 4;                 // chunk offset within k16 pair
    const int brow = wn * 32 + ((lane >> 4) << 3) + (lane & 7);   // + p*16
    const int bcho = (lane >> 3) & 1;

#pragma unroll 1
    for (int kt = -1; kt < 16; kt++) {
        if (kt < 15) {
            const int s = (kt + 1) & 1, k0 = (kt + 1) * 64;
#pragma unroll
            for (int i = 0; i < 4; i++) {
                int r = lr + i * 32;
                CP16(swad(sb + G_A(s), r, lj), A + (size_t)(m0 + r) * D_MODEL + k0 + lj * 8);
                CP16(swad(sb + G_B(s), r, lj), W + (size_t)(n0 + r) * D_MODEL + k0 + lj * 8);
            }
            CPC;
        }
        if (kt < 0) continue;
        if (kt < 15) { CPW(1); } else { CPW(0); }
        __syncthreads();

        const int s = kt & 1;
        const uint32_t ab = sb + G_A(s), bbs = sb + G_B(s);
#pragma unroll
        for (int g = 0; g < 4; g++) {           // k16 groups within k64
            uint32_t a[4][4], bb[2][4];
#pragma unroll
            for (int mi = 0; mi < 4; mi++)
                ldsm4(a[mi], swad(ab, arow + mi * 16, g * 2 + acho));
#pragma unroll
            for (int p = 0; p < 2; p++)
                ldsm4(bb[p], swad(bbs, brow + p * 16, g * 2 + bcho));
#pragma unroll
            for (int mi = 0; mi < 4; mi++)
#pragma unroll
                for (int ni = 0; ni < 4; ni++)
                    mma_f16(acc[mi][ni], a[mi], &bb[ni >> 1][(ni & 1) << 1]);
        }
        __syncthreads();
    }

#pragma unroll
    for (int mi = 0; mi < 4; mi++) {
        int r = m0 + wm * 64 + mi * 16 + grp;
#pragma unroll
        for (int ni = 0; ni < 4; ni++) {
            int c = n0 + wn * 32 + ni * 8 + (four << 1);
            float b0 = bias[c], b1 = bias[c + 1];
            if (HALF_OUT) {
                __half* C = (__half*)Cv;
                *(__half2*)(C + (size_t)r * D_MODEL + c) =
                    __floats2half2_rn(acc[mi][ni][0] + b0, acc[mi][ni][1] + b1);
                *(__half2*)(C + (size_t)(r + 8) * D_MODEL + c) =
                    __floats2half2_rn(acc[mi][ni][2] + b0, acc[mi][ni][3] + b1);
            } else {
                float* C = (float*)Cv;
                float2 v0; v0.x = acc[mi][ni][0] + b0; v0.y = acc[mi][ni][1] + b1;
                float2 v1; v1.x = acc[mi][ni][2] + b0; v1.y = acc[mi][ni][3] + b1;
                *(float2*)(C + (size_t)r * D_MODEL + c)       = v0;
                *(float2*)(C + (size_t)(r + 8) * D_MODEL + c) = v1;
            }
        }
    }
}

__global__ __launch_bounds__(256, 2) void qkv_gemm_kernel(
    const float* __restrict__ bq, const float* __restrict__ bk, const float* __restrict__ bv) {
    if (blockIdx.z == 0)      gemm_body<true>(g_xh, g_Wqh, bq, g_Qh);
    else if (blockIdx.z == 1) gemm_body<true>(g_xh, g_Wkh, bk, g_Kh);
    else                      gemm_body<true>(g_xh, g_Wvh, bv, g_Vh);
}
__global__ __launch_bounds__(256, 2) void out_gemm_kernel(
    const float* __restrict__ bo, float* __restrict__ out) {
    gemm_body<false>(g_AOh, g_Woh, bo, out);
}

// ---------------- attention fp16 (R6 skeleton: 4 warps x 32 q-rows) -------------
// smem (bytes): Q 16K @0, K 8K @16384, V 8K @24576, P 16K @32768 = 48K total.
#define QSB 0
#define KSB 16384
#define VSB 24576
#define PSB 32768
#define ATTN_SMEM 49152

__global__ __launch_bounds__(128, 2) void attn_kernel(const float* __restrict__ dbias) {
    extern __shared__ __align__(128) char smc[];
    const uint32_t sb = (uint32_t)__cvta_generic_to_shared(smc);
    const int h = blockIdx.x, q0 = blockIdx.y * 128;
    const int tid = threadIdx.x, warp = tid >> 5, lane = tid & 31;
    const int grp = lane >> 2, four = lane & 3;
    const int mb = warp * 32;

    const int lr = tid >> 3, lj = tid & 7;     // loader: row, chunk

    // stage Q tile (128 rows x 128B)
#pragma unroll
    for (int i = 0; i < 8; i++) {
        int r = lr + i * 16;
        CP16(swad(sb + QSB, r, lj), g_Qh + (size_t)(q0 + r) * D_MODEL + h * 64 + lj * 8);
    }
    CPC;

    float Of[2][8][4], Or[2][8][4];
#pragma unroll
    for (int mi = 0; mi < 2; mi++)
#pragma unroll
        for (int ni = 0; ni < 8; ni++)
#pragma unroll
            for (int j = 0; j < 4; j++) { Of[mi][ni][j] = 0.f; Or[mi][ni][j] = 0.f; }
    float lsum[2][2] = {{0.f, 0.f}, {0.f, 0.f}};

    const float* brow[2][2];
#pragma unroll
    for (int mi = 0; mi < 2; mi++) {
        brow[mi][0] = dbias + (size_t)(q0 + mb + mi * 16 + grp) * N_SEQ;
        brow[mi][1] = brow[mi][0] + (size_t)8 * N_SEQ;
    }

    const int arow0 = mb + (lane & 15);          // + mi*16 ; A-frag rows (Q and P)
    const int acho  = lane >> 4;
    const int brow0 = ((lane >> 4) << 3) + (lane & 7);  // + p*16 ; B-frag rows (K and V)
    const int bcho  = (lane >> 3) & 1;

#pragma unroll 1
    for (int kc = 0; kc < 32; kc++) {
        const int key0 = kc * 64;
        __syncthreads();                         // prior chunk fully consumed
#pragma unroll
        for (int i = 0; i < 4; i++) {
            int r = lr + i * 16;                 // 0..63
            CP16(swad(sb + KSB, r, lj), g_Kh + (size_t)(key0 + r) * D_MODEL + h * 64 + lj * 8);
        }
        CPC;
#pragma unroll
        for (int i = 0; i < 4; i++) {
            int r = lr + i * 16;                 // d-rows 0..63
            CP16(swad(sb + VSB, r, lj), g_Vth + (size_t)(h * 64 + r) * N_SEQ + key0 + lj * 8);
        }
        CPC;
        CPW(1);                                  // Q (first iter) + K ready
        __syncthreads();

        // S = Q @ K^T  (32 x 64 per warp), 4 k16 groups
        float s[2][8][4];
#pragma unroll
        for (int mi = 0; mi < 2; mi++)
#pragma unroll
            for (int ni = 0; ni < 8; ni++)
#pragma unroll
                for (int j = 0; j < 4; j++) s[mi][ni][j] = 0.f;
#pragma unroll
        for (int g = 0; g < 4; g++) {
            uint32_t a[2][4], bb[4][4];
#pragma unroll
            for (int mi = 0; mi < 2; mi++)
                ldsm4(a[mi], swad(sb + QSB, arow0 + mi * 16, g * 2 + acho));
#pragma unroll
            for (int p = 0; p < 4; p++)
                ldsm4(bb[p], swad(sb + KSB, brow0 + p * 16, g * 2 + bcho));
#pragma unroll
            for (int mi = 0; mi < 2; mi++)
#pragma unroll
                for (int ni = 0; ni < 8; ni++)
                    mma_f16(s[mi][ni], a[mi], &bb[ni >> 1][(ni & 1) << 1]);
        }

        // P = exp(scale*S - bias); stage P (fp16) to smem
#pragma unroll
        for (int mi = 0; mi < 2; mi++) {
            const int rA = mb + mi * 16 + grp, rB = rA + 8;
#pragma unroll
            for (int ni = 0; ni < 8; ni++) {
                int c = ni * 8 + (four << 1);
                float2 bA = *(const float2*)(brow[mi][0] + key0 + c);
                float2 bB = *(const float2*)(brow[mi][1] + key0 + c);
                float p0 = __expf(fmaf(s[mi][ni][0], ATTN_SCALE, -bA.x));
                float p1 = __expf(fmaf(s[mi][ni][1], ATTN_SCALE, -bA.y));
                float p2 = __expf(fmaf(s[mi][ni][2], ATTN_SCALE, -bB.x));
                float p3 = __expf(fmaf(s[mi][ni][3], ATTN_SCALE, -bB.y));
                lsum[mi][0] += p0 + p1; lsum[mi][1] += p2 + p3;
                // chunk = ni, byte-in-chunk = four*4
                *(uint32_t*)(smc + PSB + rA * 128 + (((ni) ^ (rA & 7)) << 4) + four * 4) = packh2(p0, p1);
                *(uint32_t*)(smc + PSB + rB * 128 + (((ni) ^ (rB & 7)) << 4) + four * 4) = packh2(p2, p3);
            }
        }
        __syncwarp();                            // own-warp P rows visible

        CPW(0);                                  // V arrived
        __syncthreads();                         // V visible CTA-wide

        // Or += P @ V  (B operand from Vt: rows = d, cols = keys)
#pragma unroll
        for (int g = 0; g < 4; g++) {
            uint32_t a[2][4], bb[4][4];
#pragma unroll
            for (int mi = 0; mi < 2; mi++)
                ldsm4(a[mi], swad(sb + PSB, arow0 + mi * 16, g * 2 + acho));
#pragma unroll
            for (int p = 0; p < 4; p++)
                ldsm4(bb[p], swad(sb + VSB, brow0 + p * 16, g * 2 + bcho));
#pragma unroll
            for (int mi = 0; mi < 2; mi++)
#pragma unroll
                for (int ni = 0; ni < 8; ni++)
                    mma_f16(Or[mi][ni], a[mi], &bb[ni >> 1][(ni & 1) << 1]);
        }

        // 256-key block boundary: normalize & accumulate
        if ((kc & 3) == 3) {
#pragma unroll
            for (int mi = 0; mi < 2; mi++) {
                float L0 = lsum[mi][0], L1 = lsum[mi][1];
                L0 += __shfl_xor_sync(0xffffffffu, L0, 1);
                L0 += __shfl_xor_sync(0xffffffffu, L0, 2);
                L1 += __shfl_xor_sync(0xffffffffu, L1, 1);
                L1 += __shfl_xor_sync(0xffffffffu, L1, 2);
                float i0 = 1.0f / L0, i1 = 1.0f / L1;
#pragma unroll
                for (int ni = 0; ni < 8; ni++) {
                    Of[mi][ni][0] += Or[mi][ni][0] * i0;
                    Of[mi][ni][1] += Or[mi][ni][1] * i0;
                    Of[mi][ni][2] += Or[mi][ni][2] * i1;
                    Of[mi][ni][3] += Or[mi][ni][3] * i1;
                    Or[mi][ni][0] = Or[mi][ni][1] = Or[mi][ni][2] = Or[mi][ni][3] = 0.f;
                }
                lsum[mi][0] = 0.f; lsum[mi][1] = 0.f;
            }
        }
    }

    const float r8 = 1.0f / (8.0f + 1e-8f);      // exact normalizer: nb = 8
#pragma unroll
    for (int mi = 0; mi < 2; mi++) {
#pragma unroll
        for (int ni = 0; ni < 8; ni++) {
            int c = h * 64 + ni * 8 + (four << 1);
            size_t o0 = (size_t)(q0 + mb + mi * 16 + grp) * D_MODEL + c;
            size_t o1 = o0 + (size_t)8 * D_MODEL;
            *(__half2*)(g_AOh + o0) = __floats2half2_rn(Of[mi][ni][0] * r8, Of[mi][ni][1] * r8);
            *(__half2*)(g_AOh + o1) = __floats2half2_rn(Of[mi][ni][2] * r8, Of[mi][ni][3] * r8);
        }
    }
}

// ---------------- launch ---------------------------------------------------------
extern "C" void kernel_launch(void* const* d_in, const int* in_sizes, int n_in,
                              void* d_out, int out_size) {
    const float* x  = (const float*)d_in[0];
    const float* db = (const float*)d_in[1];
    const float* Wq = (const float*)d_in[2];
    const float* bq = (const float*)d_in[3];
    const float* Wk = (const float*)d_in[4];
    const float* bk = (const float*)d_in[5];
    const float* Wv = (const float*)d_in[6];
    const float* bv = (const float*)d_in[7];
    const float* Wo = (const float*)d_in[8];
    const float* bo = (const float*)d_in[9];
    float* out = (float*)d_out;

    cudaFuncSetAttribute(qkv_gemm_kernel, cudaFuncAttributeMaxDynamicSharedMemorySize, GEMM_SMEM);
    cudaFuncSetAttribute(out_gemm_kernel, cudaFuncAttributeMaxDynamicSharedMemorySize, GEMM_SMEM);
    cudaFuncSetAttribute(attn_kernel,     cudaFuncAttributeMaxDynamicSharedMemorySize, ATTN_SMEM);

    prep_kernel<<<dim3(2048, 5), 256>>>((const float4*)x, (const float4*)Wq,
                                        (const float4*)Wk, (const float4*)Wv,
                                        (const float4*)Wo);
    qkv_gemm_kernel<<<dim3(16, 8, 3), 256, GEMM_SMEM>>>(bq, bk, bv);
    transposeV_kernel<<<dim3(32, 64), 256>>>();
    attn_kernel<<<dim3(16, 16), 128, ATTN_SMEM>>>(db);
    out_gemm_kernel<<<dim3(16, 8), 256, GEMM_SMEM>>>(bo, out);
}